// round 2
// baseline (speedup 1.0000x reference)
#include <cuda_runtime.h>

// ---------------------------------------------------------------------------
// PixelEachSubstitutor: per-pixel tiny transformer, structure-exploited.
// R2: LDS-traffic reduction (register-cached operand rows in all hot loops),
//     warp-shuffle LayerNorms, full-width kc/vc phase.
// ---------------------------------------------------------------------------

__device__ float g_y1[320];   // post-SA, post-LN1 decoder state (10 x 32)
__device__ float g_qc[320];   // cross-attention queries y1 @ WqCA^T (10 x 32)
__device__ float g_S[32];     // sum_{p=9..80} ffV_w[v][p]

__device__ __forceinline__ float fast_exp(float x) {
    float t = x * 1.4426950408889634f;
    t = fmaxf(t, -110.0f);
    float z = t + 12582912.0f;                  // 1.5 * 2^23
    int   n = __float_as_int(z) - 0x4B400000;   // = rint(t)
    float r = t - (z - 12582912.0f);            // in [-0.5, 0.5]
    float p = 1.3333558e-3f;
    p = fmaf(p, r, 9.6181291e-3f);
    p = fmaf(p, r, 5.5504109e-2f);
    p = fmaf(p, r, 2.4022651e-1f);
    p = fmaf(p, r, 6.9314718e-1f);
    p = fmaf(p, r, 1.0f);
    return __int_as_float((n + 127) << 23) * p;
}

__device__ __forceinline__ float warp_sum(float v) {
    v += __shfl_xor_sync(0xffffffffu, v, 16);
    v += __shfl_xor_sync(0xffffffffu, v, 8);
    v += __shfl_xor_sync(0xffffffffu, v, 4);
    v += __shfl_xor_sync(0xffffffffu, v, 2);
    v += __shfl_xor_sync(0xffffffffu, v, 1);
    return v;
}

// ---------------------------------------------------------------------------
// Precompute kernel: 1 block, 320 threads. Pixel-independent decoder SA block.
// ---------------------------------------------------------------------------
__global__ void __launch_bounds__(320) precompute_kernel(
    const float* __restrict__ Vf,
    const float* __restrict__ sa_in,
    const float* __restrict__ sa_out,
    const float* __restrict__ dln1,
    const float* __restrict__ ca_in,
    const float* __restrict__ ffv)
{
    __shared__ float qs[320], ks[320], vs[320], os_[320], rr[320], y1s[320];
    int t = threadIdx.x;
    int i = t >> 5, h = t & 31;

    float aq = 0.f, ak = 0.f, av = 0.f;
    #pragma unroll 8
    for (int v = 0; v < 32; v++) {
        float f = Vf[i * 32 + v];
        aq = fmaf(sa_in[h * 32 + v], f, aq);
        ak = fmaf(sa_in[(32 + h) * 32 + v], f, ak);
        av = fmaf(sa_in[(64 + h) * 32 + v], f, av);
    }
    qs[t] = aq; ks[t] = ak; vs[t] = av;
    __syncthreads();

    {
        float qv = qs[i * 32 + h];
        float m = -1e30f;
        #pragma unroll
        for (int j = 0; j < 10; j++) m = fmaxf(m, qv * ks[j * 32 + h]);
        float den = 0.f, num = 0.f;
        #pragma unroll
        for (int j = 0; j < 10; j++) {
            float e = fast_exp(fmaf(qv, ks[j * 32 + h], -m));
            den += e;
            num = fmaf(e, vs[j * 32 + h], num);
        }
        os_[t] = num / den;
    }
    __syncthreads();

    {
        int c = h;
        float acc = 0.f;
        #pragma unroll 8
        for (int hh = 0; hh < 32; hh++)
            acc = fmaf(sa_out[c * 32 + hh], os_[i * 32 + hh], acc);
        rr[t] = Vf[i * 32 + c] + acc;
    }
    __syncthreads();

    if (t < 10) {
        float mean = 0.f;
        for (int c = 0; c < 32; c++) mean += rr[t * 32 + c];
        mean *= (1.0f / 32.0f);
        float var = 0.f;
        for (int c = 0; c < 32; c++) { float d = rr[t * 32 + c] - mean; var = fmaf(d, d, var); }
        var *= (1.0f / 32.0f);
        float inv = rsqrtf(var + 1e-5f);
        for (int c = 0; c < 32; c++) {
            float yv = (rr[t * 32 + c] - mean) * inv * dln1[c];
            y1s[t * 32 + c] = yv;
            g_y1[t * 32 + c] = yv;
        }
    }
    __syncthreads();

    {
        float acc = 0.f;
        #pragma unroll 8
        for (int v = 0; v < 32; v++)
            acc = fmaf(ca_in[h * 32 + v], y1s[i * 32 + v], acc);
        g_qc[t] = acc;
    }
    if (t < 32) {
        float s = 0.f;
        for (int p = 9; p < 81; p++) s += ffv[t * 81 + p];
        g_S[t] = s;
    }
}

// ---------------------------------------------------------------------------
// Main kernel: one block (128 threads) per pixel, 14400 blocks.
// ---------------------------------------------------------------------------
__global__ void __launch_bounds__(128) main_kernel(
    const float* __restrict__ x,
    const float* __restrict__ enc_in, const float* __restrict__ enc_out,
    const float* __restrict__ el1, const float* __restrict__ el2,
    const float* __restrict__ eln1, const float* __restrict__ eln2,
    const float* __restrict__ ffv,
    const float* __restrict__ ca_in, const float* __restrict__ ca_out,
    const float* __restrict__ dl1, const float* __restrict__ dl2,
    const float* __restrict__ dln2, const float* __restrict__ dln3,
    const float* __restrict__ wd0, const float* __restrict__ wd1,
    float* __restrict__ out)
{
    // ---- weights ----
    __shared__ float sWin[363];
    __shared__ float sWout[121];
    __shared__ float sLin1[11], sLin2[11], sLn1[11], sLn2[11];
    __shared__ float sFfvT[9 * 32];      // [p*32+v]
    __shared__ float sS[32];
    __shared__ float sQc[320];
    __shared__ float sY1[320];
    __shared__ float sWk[32 * 33];       // [h*33+v]
    __shared__ float sWv[32 * 33];
    __shared__ float sWo2[32 * 33];      // [c*33+h]
    __shared__ float sDlin1[32], sDlin2[32], sDln2w[32], sDln3w[32];
    __shared__ float sWd0[8 * 33];       // [k*33+c]
    __shared__ float sWd1[8];
    // ---- activations ----
    __shared__ float f9s[9 * 12];
    __shared__ float qes[9 * 12], kes[9 * 12], ves[9 * 12];
    __shared__ float scs[9 * 12];
    __shared__ float ous[12];
    __shared__ float invd[9];
    __shared__ float ggs[10 * 12];
    __shared__ float f2s[10 * 12];
    __shared__ __align__(16) float mems[11 * 36];  // [c*36+v]
    __shared__ float kcs[11 * 33], vcs[11 * 33];   // [j*33+h]
    __shared__ float oas[320];
    __shared__ float y2s[10 * 33];
    __shared__ float y3s[10 * 33];
    __shared__ float hks[80];

    const int tid = threadIdx.x;
    const int b = blockIdx.x;
    const int n = b / 900;
    const int rem = b % 900;
    const int pi = rem / 30;
    const int pj = rem % 30;
    const int lane = tid & 31;
    const int wrp  = tid >> 5;

    // ---- stage weights ----
    for (int t = tid; t < 363; t += 128) sWin[t] = enc_in[t];
    for (int t = tid; t < 121; t += 128) sWout[t] = enc_out[t];
    if (tid < 11) {
        sLin1[tid] = el1[tid]; sLin2[tid] = el2[tid];
        sLn1[tid] = eln1[tid]; sLn2[tid] = eln2[tid];
    }
    for (int t = tid; t < 288; t += 128) {
        int v = t / 9, p = t % 9;
        sFfvT[p * 32 + v] = ffv[v * 81 + p];
    }
    if (tid < 32) {
        sS[tid] = g_S[tid];
        sDlin1[tid] = dl1[tid]; sDlin2[tid] = dl2[tid];
        sDln2w[tid] = dln2[tid]; sDln3w[tid] = dln3[tid];
    }
    for (int t = tid; t < 320; t += 128) { sQc[t] = g_qc[t]; sY1[t] = g_y1[t]; }
    for (int t = tid; t < 1024; t += 128) {
        int hh = t >> 5, v = t & 31;
        sWk[hh * 33 + v] = ca_in[(32 + hh) * 32 + v];
        sWv[hh * 33 + v] = ca_in[(64 + hh) * 32 + v];
        sWo2[hh * 33 + v] = ca_out[t];
    }
    for (int t = tid; t < 256; t += 128) {
        int k = t >> 5, c = t & 31;
        sWd0[k * 33 + c] = wd0[t];
    }
    if (tid < 8) sWd1[tid] = wd1[tid];

    // ---- build f9 ----
    for (int t = tid; t < 99; t += 128) {
        int p = t / 11, c = t % 11;
        float val;
        if (c == 10) {
            val = 1.0f;
        } else {
            int ii = pi + p / 3 - 1, jj = pj + p % 3 - 1;
            val = (ii >= 0 && ii < 30 && jj >= 0 && jj < 30)
                      ? x[((n * 10 + c) * 30 + ii) * 30 + jj] : 0.0f;
        }
        f9s[p * 12 + c] = val;
    }
    __syncthreads();

    // ---- encoder qkv: thread = (which, a, pgroup), weight row register-cached ----
    if (tid < 99) {
        int which = tid / 33, r = tid % 33;
        int a = r / 3, pg = r % 3;
        float wr[11];
        #pragma unroll
        for (int c = 0; c < 11; c++) wr[c] = sWin[(which * 11 + a) * 11 + c];
        float* dst = (which == 0) ? qes : (which == 1) ? kes : ves;
        #pragma unroll
        for (int pp = 0; pp < 3; pp++) {
            int p = pg * 3 + pp;
            const float* f = &f9s[p * 12];
            float acc = 0.f;
            #pragma unroll
            for (int c = 0; c < 11; c++) acc = fmaf(wr[c], f[c], acc);
            dst[p * 12 + a] = acc;
        }
    }
    __syncthreads();

    // ---- 9x9 scores (q row cached) + uniform-row value mean ----
    if (tid < 27) {
        int i = tid / 3, jg = tid % 3;
        float qv[11];
        #pragma unroll
        for (int a = 0; a < 11; a++) qv[a] = qes[i * 12 + a];
        #pragma unroll
        for (int jj = 0; jj < 3; jj++) {
            int j = jg * 3 + jj;
            float acc = 0.f;
            #pragma unroll
            for (int a = 0; a < 11; a++) acc = fmaf(qv[a], kes[j * 12 + a], acc);
            scs[i * 12 + j] = acc * 0.30151134457776363f;  // 1/sqrt(11)
        }
    } else if (tid >= 96 && tid < 107) {
        int a = tid - 96;
        float s = 0.f;
        #pragma unroll
        for (int j = 0; j < 9; j++) s += ves[j * 12 + a];
        ous[a] = s * (1.0f / 81.0f);
    }
    __syncthreads();

    // ---- row softmax with +72 zero-key correction ----
    if (tid < 9) {
        int i = tid;
        float m = 0.0f;
        #pragma unroll
        for (int j = 0; j < 9; j++) m = fmaxf(m, scs[i * 12 + j]);
        float sum = 72.0f * fast_exp(-m);
        #pragma unroll
        for (int j = 0; j < 9; j++) {
            float e = fast_exp(scs[i * 12 + j] - m);
            scs[i * 12 + j] = e;
            sum += e;
        }
        invd[i] = 1.0f / sum;
    }
    __syncthreads();

    // ---- attn @ v: thread = (a, igroup), value column cached ----
    if (tid < 33) {
        int a = tid / 3, ig = tid % 3;
        float vv[9];
        #pragma unroll
        for (int j = 0; j < 9; j++) vv[j] = ves[j * 12 + a];
        #pragma unroll
        for (int ii = 0; ii < 3; ii++) {
            int i = ig * 3 + ii;
            float acc = 0.f;
            #pragma unroll
            for (int j = 0; j < 9; j++) acc = fmaf(scs[i * 12 + j], vv[j], acc);
            qes[i * 12 + a] = acc * invd[i];
        }
    }
    __syncthreads();

    // ---- out_proj + residual -> ggs: thread = (c, igroup), W row cached ----
    if (tid < 44) {
        int c = tid / 4, ig = tid % 4;
        float wr[11];
        #pragma unroll
        for (int a = 0; a < 11; a++) wr[a] = sWout[c * 11 + a];
        #pragma unroll
        for (int ii = 0; ii < 3; ii++) {
            int i = ig + 4 * ii;
            if (i < 10) {
                const float* osrc = (i < 9) ? &qes[i * 12] : ous;
                float acc = (i < 9) ? f9s[i * 12 + c] : 0.0f;
                #pragma unroll
                for (int a = 0; a < 11; a++) acc = fmaf(wr[a], osrc[a], acc);
                ggs[i * 12 + c] = acc;
            }
        }
    }
    __syncthreads();

    // ---- encoder LN1 + FFN + LN2: warp per row, shuffle reductions ----
    {
        float w1  = (lane < 11) ? sLn1[lane]  : 0.f;
        float w2  = (lane < 11) ? sLn2[lane]  : 0.f;
        float wl1 = (lane < 11) ? sLin1[lane] : 0.f;
        float wl2 = (lane < 11) ? sLin2[lane] : 0.f;
        for (int r = wrp; r < 10; r += 4) {
            float l = (lane < 11) ? ggs[r * 12 + lane] : 0.f;
            float mean = warp_sum(l) * (1.0f / 11.0f);
            float d = (lane < 11) ? (l - mean) : 0.f;
            float var = warp_sum(d * d) * (1.0f / 11.0f);
            float inv = rsqrtf(var + 1e-5f);
            l = d * inv * w1;
            float s1 = fmaxf(warp_sum(l * wl1), 0.0f);
            l = fmaf(s1, wl2, l);
            float mean2 = warp_sum(l) * (1.0f / 11.0f);
            float d2 = (lane < 11) ? (l - mean2) : 0.f;
            float var2 = warp_sum(d2 * d2) * (1.0f / 11.0f);
            float inv2 = rsqrtf(var2 + 1e-5f);
            if (lane < 11) f2s[r * 12 + lane] = d2 * inv2 * w2;
        }
    }
    __syncthreads();

    // ---- mem: thread = (v, cgroup), ffv column register-cached ----
    {
        int v = lane, cg = wrp;
        float fv[9];
        #pragma unroll
        for (int p = 0; p < 9; p++) fv[p] = sFfvT[p * 32 + v];
        float Sv = sS[v];
        #pragma unroll
        for (int cc = 0; cc < 3; cc++) {
            int c = cg + 4 * cc;
            if (c < 11) {
                float acc = f2s[9 * 12 + c] * Sv;
                #pragma unroll
                for (int p = 0; p < 9; p++) acc = fmaf(f2s[p * 12 + c], fv[p], acc);
                mems[c * 36 + v] = acc;
            }
        }
    }
    __syncthreads();

    // ---- kc/vc: thread = (h, which, jhalf), weight row register-cached ----
    {
        int h = lane, which = (tid >> 5) & 1, jh = tid >> 6;
        const float* W = which ? &sWv[h * 33] : &sWk[h * 33];
        float w[32];
        #pragma unroll
        for (int v = 0; v < 32; v++) w[v] = W[v];
        float* dst = which ? vcs : kcs;
        for (int j = jh; j < 11; j += 2) {
            const float4* mr = (const float4*)&mems[j * 36];
            float acc = 0.f;
            #pragma unroll
            for (int q4 = 0; q4 < 8; q4++) {
                float4 m4 = mr[q4];
                acc = fmaf(w[4 * q4 + 0], m4.x, acc);
                acc = fmaf(w[4 * q4 + 1], m4.y, acc);
                acc = fmaf(w[4 * q4 + 2], m4.z, acc);
                acc = fmaf(w[4 * q4 + 3], m4.w, acc);
            }
            dst[j * 33 + h] = acc;
        }
    }
    __syncthreads();

    // ---- cross-attention (hd=1): thread = (h, igroup), 2-pass, kc/vc amortized ----
    {
        int h = lane, ig = wrp;
        int i0 = ig, i1 = ig + 4, i2 = (ig < 2) ? ig + 8 : ig;
        float q0 = sQc[i0 * 32 + h], q1 = sQc[i1 * 32 + h], q2 = sQc[i2 * 32 + h];
        float m0 = -1e30f, m1 = -1e30f, m2 = -1e30f;
        #pragma unroll
        for (int j = 0; j < 11; j++) {
            float kc = kcs[j * 33 + h];
            m0 = fmaxf(m0, q0 * kc);
            m1 = fmaxf(m1, q1 * kc);
            m2 = fmaxf(m2, q2 * kc);
        }
        float d0 = 0.f, d1 = 0.f, d2 = 0.f, n0 = 0.f, n1 = 0.f, n2 = 0.f;
        #pragma unroll
        for (int j = 0; j < 11; j++) {
            float kc = kcs[j * 33 + h];
            float vc = vcs[j * 33 + h];
            float e0 = fast_exp(fmaf(q0, kc, -m0)); d0 += e0; n0 = fmaf(e0, vc, n0);
            float e1 = fast_exp(fmaf(q1, kc, -m1)); d1 += e1; n1 = fmaf(e1, vc, n1);
            float e2 = fast_exp(fmaf(q2, kc, -m2)); d2 += e2; n2 = fmaf(e2, vc, n2);
        }
        oas[i0 * 32 + h] = n0 / d0;
        oas[i1 * 32 + h] = n1 / d1;
        if (ig < 2) oas[i2 * 32 + h] = n2 / d2;
    }
    __syncthreads();

    // ---- CA out projection + residual: thread = (c, igroup), W cached per hh ----
    {
        int c = lane, ig = wrp;
        int i0 = ig, i1 = ig + 4, i2 = (ig < 2) ? ig + 8 : ig;
        float a0 = 0.f, a1 = 0.f, a2 = 0.f;
        #pragma unroll
        for (int hh = 0; hh < 32; hh++) {
            float w = sWo2[c * 33 + hh];
            a0 = fmaf(w, oas[i0 * 32 + hh], a0);
            a1 = fmaf(w, oas[i1 * 32 + hh], a1);
            a2 = fmaf(w, oas[i2 * 32 + hh], a2);
        }
        y2s[i0 * 33 + c] = sY1[i0 * 32 + c] + a0;
        y2s[i1 * 33 + c] = sY1[i1 * 32 + c] + a1;
        if (ig < 2) y2s[i2 * 33 + c] = sY1[i2 * 32 + c] + a2;
    }
    __syncthreads();

    // ---- decoder LN2 + FFN + LN3: warp per row, shuffle reductions ----
    {
        float w2  = sDln2w[lane];
        float w3  = sDln3w[lane];
        float wl1 = sDlin1[lane];
        float wl2 = sDlin2[lane];
        for (int r = wrp; r < 10; r += 4) {
            float l = y2s[r * 33 + lane];
            float mean = warp_sum(l) * (1.0f / 32.0f);
            float d = l - mean;
            float var = warp_sum(d * d) * (1.0f / 32.0f);
            float inv = rsqrtf(var + 1e-5f);
            l = d * inv * w2;
            float s1 = fmaxf(warp_sum(l * wl1), 0.0f);
            l = fmaf(s1, wl2, l);
            float mean2 = warp_sum(l) * (1.0f / 32.0f);
            float d2 = l - mean2;
            float var2 = warp_sum(d2 * d2) * (1.0f / 32.0f);
            float inv2 = rsqrtf(var2 + 1e-5f);
            y3s[r * 33 + lane] = d2 * inv2 * w3;
        }
    }
    __syncthreads();

    // ---- head: relu(y3 @ Wd0^T) @ Wd1^T ----
    if (tid < 80) {
        int i = tid >> 3, k = tid & 7;
        float acc = 0.f;
        #pragma unroll
        for (int c = 0; c < 32; c++) acc = fmaf(sWd0[k * 33 + c], y3s[i * 33 + c], acc);
        hks[i * 8 + k] = fmaxf(acc, 0.0f);
    }
    __syncthreads();
    if (tid < 10) {
        float z = 0.f;
        #pragma unroll
        for (int k = 0; k < 8; k++) z = fmaf(hks[tid * 8 + k], sWd1[k], z);
        out[((n * 10 + tid) * 30 + pi) * 30 + pj] = z;
    }
}

extern "C" void kernel_launch(void* const* d_in, const int* in_sizes, int n_in,
                              void* d_out, int out_size) {
    const float* x       = (const float*)d_in[0];
    const float* Vf      = (const float*)d_in[1];
    const float* enc_in  = (const float*)d_in[2];
    const float* enc_out = (const float*)d_in[3];
    const float* el1     = (const float*)d_in[4];
    const float* el2     = (const float*)d_in[5];
    const float* eln1    = (const float*)d_in[6];
    const float* eln2    = (const float*)d_in[7];
    const float* ffv     = (const float*)d_in[8];
    const float* sa_in   = (const float*)d_in[9];
    const float* sa_out  = (const float*)d_in[10];
    const float* ca_in   = (const float*)d_in[11];
    const float* ca_out  = (const float*)d_in[12];
    const float* dl1     = (const float*)d_in[13];
    const float* dl2     = (const float*)d_in[14];
    const float* dln1    = (const float*)d_in[15];
    const float* dln2    = (const float*)d_in[16];
    const float* dln3    = (const float*)d_in[17];
    const float* wd0     = (const float*)d_in[18];
    const float* wd1     = (const float*)d_in[19];

    precompute_kernel<<<1, 320>>>(Vf, sa_in, sa_out, dln1, ca_in, ffv);
    main_kernel<<<14400, 128>>>(x, enc_in, enc_out, el1, el2, eln1, eln2, ffv,
                                ca_in, ca_out, dl1, dl2, dln2, dln3, wd0, wd1,
                                (float*)d_out);
}

// round 3
// speedup vs baseline: 1.1557x; 1.1557x over previous
#include <cuda_runtime.h>

// ---------------------------------------------------------------------------
// PixelEachSubstitutor R3: algebraic hoisting.
//  - Gq/Gk/Gvp 1x1-conv fields precomputed once (qkv + out_proj leave the pixel loop)
//  - A_k/A_v = Wk@ffv9 folding: 'mem' GEMM deleted, kc/vc 10-deep
//  - decoder SA block precomputed (pixel-independent)
//  - no-max cross-attn softmax, FMA-pipe poly exp
// ---------------------------------------------------------------------------

__device__ float g_y1[320];    // post-SA+LN1 decoder state (10 x 32)
__device__ float g_qc[320];    // cross-attn queries (10 x 32)
__device__ float g_Ak[352];    // [h*11+p], p=0..8: Wk@ffv9 ; p=9: Wk@S
__device__ float g_Av[352];
__device__ float g_M[110];     // [a*10+c] : enc_out @ Wv[:, :10]
__device__ float g_bq[11], g_bk[11], g_bvp[11];
__device__ float g_G[3 * 16 * 11 * 1024];  // [(w*16+n)*11+a][32][32], zero-padded border

__device__ __forceinline__ float fast_exp(float x) {
    float t = x * 1.4426950408889634f;
    t = fmaxf(t, -110.0f);
    float z = t + 12582912.0f;                  // 1.5 * 2^23
    int   n = __float_as_int(z) - 0x4B400000;   // rint(t)
    float r = t - (z - 12582912.0f);            // [-0.5, 0.5]
    float p = 1.3333558e-3f;
    p = fmaf(p, r, 9.6181291e-3f);
    p = fmaf(p, r, 5.5504109e-2f);
    p = fmaf(p, r, 2.4022651e-1f);
    p = fmaf(p, r, 6.9314718e-1f);
    p = fmaf(p, r, 1.0f);
    return __int_as_float((n + 127) << 23) * p;
}

__device__ __forceinline__ float warp_sum(float v) {
    v += __shfl_xor_sync(0xffffffffu, v, 16);
    v += __shfl_xor_sync(0xffffffffu, v, 8);
    v += __shfl_xor_sync(0xffffffffu, v, 4);
    v += __shfl_xor_sync(0xffffffffu, v, 2);
    v += __shfl_xor_sync(0xffffffffu, v, 1);
    return v;
}

// ---------------------------------------------------------------------------
// Precompute 1: decoder SA block + folded weight products. 1 block, 320 thr.
// ---------------------------------------------------------------------------
__global__ void __launch_bounds__(320) precompute_kernel(
    const float* __restrict__ Vf,       // (10,32)
    const float* __restrict__ sa_in,    // (96,32)
    const float* __restrict__ sa_out,   // (32,32)
    const float* __restrict__ dln1,     // (32)
    const float* __restrict__ ca_in,    // (96,32)
    const float* __restrict__ ffv,      // (32,81)
    const float* __restrict__ enc_in,   // (33,11)
    const float* __restrict__ enc_out)  // (11,11)
{
    __shared__ float qs[320], ks[320], vs[320], os_[320], rr[320], y1s[320];
    __shared__ float sS[32];
    int t = threadIdx.x;
    int i = t >> 5, h = t & 31;

    if (t < 32) {
        float s = 0.f;
        for (int p = 9; p < 81; p++) s += ffv[t * 81 + p];
        sS[t] = s;
    }

    // decoder self-attention qkv (nhead=32, hd=1)
    float aq = 0.f, ak = 0.f, av = 0.f;
    #pragma unroll 8
    for (int v = 0; v < 32; v++) {
        float f = Vf[i * 32 + v];
        aq = fmaf(sa_in[h * 32 + v], f, aq);
        ak = fmaf(sa_in[(32 + h) * 32 + v], f, ak);
        av = fmaf(sa_in[(64 + h) * 32 + v], f, av);
    }
    qs[t] = aq; ks[t] = ak; vs[t] = av;
    __syncthreads();

    {
        float qv = qs[i * 32 + h];
        float m = -1e30f;
        #pragma unroll
        for (int j = 0; j < 10; j++) m = fmaxf(m, qv * ks[j * 32 + h]);
        float den = 0.f, num = 0.f;
        #pragma unroll
        for (int j = 0; j < 10; j++) {
            float e = fast_exp(fmaf(qv, ks[j * 32 + h], -m));
            den += e;
            num = fmaf(e, vs[j * 32 + h], num);
        }
        os_[t] = num / den;
    }
    __syncthreads();

    {
        float acc = 0.f;
        #pragma unroll 8
        for (int hh = 0; hh < 32; hh++)
            acc = fmaf(sa_out[h * 32 + hh], os_[i * 32 + hh], acc);
        rr[t] = Vf[i * 32 + h] + acc;
    }
    __syncthreads();

    if (t < 10) {
        float mean = 0.f;
        for (int c = 0; c < 32; c++) mean += rr[t * 32 + c];
        mean *= (1.0f / 32.0f);
        float var = 0.f;
        for (int c = 0; c < 32; c++) { float d = rr[t * 32 + c] - mean; var = fmaf(d, d, var); }
        var *= (1.0f / 32.0f);
        float inv = rsqrtf(var + 1e-5f);
        for (int c = 0; c < 32; c++) {
            float yv = (rr[t * 32 + c] - mean) * inv * dln1[c];
            y1s[t * 32 + c] = yv;
            g_y1[t * 32 + c] = yv;
        }
    }
    __syncthreads();

    // cross-attention queries
    {
        float acc = 0.f;
        #pragma unroll 8
        for (int v = 0; v < 32; v++)
            acc = fmaf(ca_in[h * 32 + v], y1s[i * 32 + v], acc);
        g_qc[t] = acc;
    }

    // A_k / A_v folding: A[h][p] = sum_v W[h][v] * ffv[v][p] (p=9 -> S)
    {
        int hh = t / 10, p = t % 10;
        float accK = 0.f, accV = 0.f;
        #pragma unroll 8
        for (int v = 0; v < 32; v++) {
            float fv = (p < 9) ? ffv[v * 81 + p] : sS[v];
            accK = fmaf(ca_in[(32 + hh) * 32 + v], fv, accK);
            accV = fmaf(ca_in[(64 + hh) * 32 + v], fv, accV);
        }
        g_Ak[hh * 11 + p] = accK;
        g_Av[hh * 11 + p] = accV;
    }

    // M = enc_out @ Wv[:, :10]   (Wv = enc_in rows 22..32)
    if (t < 110) {
        int c = t / 10, cp = t % 10;
        float acc = 0.f;
        #pragma unroll
        for (int a = 0; a < 11; a++)
            acc = fmaf(enc_out[c * 11 + a], enc_in[(22 + a) * 11 + cp], acc);
        g_M[t] = acc;
    }

    // biases: bq, bk (ones-channel column), bvp = enc_out @ bv
    if (t < 11) {
        g_bq[t] = enc_in[t * 11 + 10];
        g_bk[t] = enc_in[(11 + t) * 11 + 10];
        float acc = 0.f;
        #pragma unroll
        for (int a = 0; a < 11; a++)
            acc = fmaf(enc_out[t * 11 + a], enc_in[(22 + a) * 11 + 10], acc);
        g_bvp[t] = acc;
    }
}

// ---------------------------------------------------------------------------
// Precompute 2: G fields (1x1 convs), zero-padded to 32x32.  needs g_M.
// 3*16*11*1024 = 540672 cells.
// ---------------------------------------------------------------------------
__global__ void __launch_bounds__(256) gfield_kernel(
    const float* __restrict__ x,       // (16,10,30,30)
    const float* __restrict__ enc_in)  // (33,11)
{
    int t = blockIdx.x * 256 + threadIdx.x;
    if (t >= 3 * 16 * 11 * 1024) return;
    int jj = t & 31;
    int ii = (t >> 5) & 31;
    int u  = t >> 10;
    int a  = u % 11;
    int q  = u / 11;
    int n  = q & 15;
    int w  = q >> 4;

    float val = 0.f;
    if (ii >= 1 && ii <= 30 && jj >= 1 && jj <= 30) {
        const float* xr = x + (n * 10) * 900 + (ii - 1) * 30 + (jj - 1);
        float acc = 0.f;
        if (w == 0) {
            #pragma unroll
            for (int c = 0; c < 10; c++) acc = fmaf(__ldg(enc_in + a * 11 + c), xr[c * 900], acc);
        } else if (w == 1) {
            #pragma unroll
            for (int c = 0; c < 10; c++) acc = fmaf(__ldg(enc_in + (11 + a) * 11 + c), xr[c * 900], acc);
        } else {
            #pragma unroll
            for (int c = 0; c < 10; c++) acc = fmaf(g_M[a * 10 + c], xr[c * 900], acc);
        }
        val = acc;
    }
    g_G[t] = val;
}

// ---------------------------------------------------------------------------
// Main kernel: one block (128 threads) per pixel, 14400 blocks.
// ---------------------------------------------------------------------------
__global__ void __launch_bounds__(128, 8) main_kernel(
    const float* __restrict__ x,
    const float* __restrict__ el1, const float* __restrict__ el2,
    const float* __restrict__ eln1, const float* __restrict__ eln2,
    const float* __restrict__ ca_out,
    const float* __restrict__ dl1, const float* __restrict__ dl2,
    const float* __restrict__ dln2, const float* __restrict__ dln3,
    const float* __restrict__ wd0, const float* __restrict__ wd1,
    float* __restrict__ out)
{
    // weights
    __shared__ float sAk[352], sAv[352];       // [h*11+p]
    __shared__ float sWo2[1056];               // [c*33+h]
    __shared__ float sQc[320], sY1[320];
    __shared__ float sDlin1[32], sDlin2[32], sDln2w[32], sDln3w[32];
    __shared__ float sWd0[264];                // [k*33+c]
    __shared__ float sWd1[8];
    __shared__ float sLin1[11], sLin2[11], sLn1[11], sLn2[11];
    // activations
    __shared__ float q9[108], k9[108], vp9[108], f9[108];  // [p*12+c]
    __shared__ float scs[108];
    __shared__ float invd[9];
    __shared__ float ggs[120], f2s[120];       // [p*12+c], rows 0..9
    __shared__ float kcs[352], vcs[352];       // [j*32+h]
    __shared__ float oas[320];                 // [i*32+h]
    __shared__ float y2s[330], y3s[330];       // [i*33+c]
    __shared__ float hks[80];

    const int tid = threadIdx.x;
    const int b = blockIdx.x;
    const int n = b / 900;
    const int rem = b % 900;
    const int pi = rem / 30;
    const int pj = rem % 30;
    const int lane = tid & 31;
    const int wrp  = tid >> 5;

    // ---- stage weights ----
    for (int t = tid; t < 352; t += 128) { sAk[t] = g_Ak[t]; sAv[t] = g_Av[t]; }
    for (int t = tid; t < 1024; t += 128) {
        int c = t >> 5, h = t & 31;
        sWo2[c * 33 + h] = ca_out[t];
    }
    for (int t = tid; t < 320; t += 128) { sQc[t] = g_qc[t]; sY1[t] = g_y1[t]; }
    if (tid < 32) {
        sDlin1[tid] = dl1[tid]; sDlin2[tid] = dl2[tid];
        sDln2w[tid] = dln2[tid]; sDln3w[tid] = dln3[tid];
    }
    for (int t = tid; t < 256; t += 128) sWd0[(t >> 5) * 33 + (t & 31)] = wd0[t];
    if (tid < 8) sWd1[tid] = wd1[tid];
    if (tid < 11) {
        sLin1[tid] = el1[tid]; sLin2[tid] = el2[tid];
        sLn1[tid] = eln1[tid]; sLn2[tid] = eln2[tid];
    }

    // ---- gather q/k/vp from G fields (+bias), f9 from x ----
    for (int t = tid; t < 396; t += 128) {
        int w = t / 99, r = t % 99;
        int p = r / 11, a = r % 11;
        int di = p / 3, dj = p % 3;
        if (w < 3) {
            float v = g_G[((w * 16 + n) * 11 + a) * 1024 + (pi + di) * 32 + (pj + dj)];
            if (w == 0)      q9[p * 12 + a]  = v + __ldg(g_bq + a);
            else if (w == 1) k9[p * 12 + a]  = v + __ldg(g_bk + a);
            else             vp9[p * 12 + a] = v + __ldg(g_bvp + a);
        } else {
            float val;
            if (a == 10) val = 1.0f;
            else {
                int ii = pi + di - 1, jj = pj + dj - 1;
                val = (ii >= 0 && ii < 30 && jj >= 0 && jj < 30)
                          ? x[((n * 10 + a) * 30 + ii) * 30 + jj] : 0.0f;
            }
            f9[p * 12 + a] = val;
        }
    }
    __syncthreads();

    // ---- 9x9 encoder scores ----
    if (tid < 81) {
        int i = tid / 9, j = tid % 9;
        float acc = 0.f;
        #pragma unroll
        for (int a = 0; a < 11; a++) acc = fmaf(q9[i * 12 + a], k9[j * 12 + a], acc);
        scs[i * 12 + j] = acc * 0.30151134457776363f;  // 1/sqrt(11)
    }
    __syncthreads();

    // ---- row softmax with +72 zero-key correction ----
    if (tid < 9) {
        int i = tid;
        float m = 0.0f;
        #pragma unroll
        for (int j = 0; j < 9; j++) m = fmaxf(m, scs[i * 12 + j]);
        float sum = 72.0f * fast_exp(-m);
        #pragma unroll
        for (int j = 0; j < 9; j++) {
            float e = fast_exp(scs[i * 12 + j] - m);
            scs[i * 12 + j] = e;
            sum += e;
        }
        invd[i] = 1.0f / sum;
    }
    __syncthreads();

    // ---- attn @ vp (already out-projected) + residual; row9 uniform ----
    if (tid < 110) {
        if (tid < 99) {
            int i = tid / 11, c = tid % 11;
            float acc = 0.f;
            #pragma unroll
            for (int j = 0; j < 9; j++) acc = fmaf(scs[i * 12 + j], vp9[j * 12 + c], acc);
            ggs[i * 12 + c] = f9[i * 12 + c] + acc * invd[i];
        } else {
            int c = tid - 99;
            float s = 0.f;
            #pragma unroll
            for (int j = 0; j < 9; j++) s += vp9[j * 12 + c];
            ggs[108 + c] = s * (1.0f / 81.0f);
        }
    }
    __syncthreads();

    // ---- encoder LN1 + FFN + LN2: warp per row ----
    {
        float w1  = (lane < 11) ? sLn1[lane]  : 0.f;
        float w2  = (lane < 11) ? sLn2[lane]  : 0.f;
        float wl1 = (lane < 11) ? sLin1[lane] : 0.f;
        float wl2 = (lane < 11) ? sLin2[lane] : 0.f;
        for (int r = wrp; r < 10; r += 4) {
            float l = (lane < 11) ? ggs[r * 12 + lane] : 0.f;
            float mean = warp_sum(l) * (1.0f / 11.0f);
            float d = (lane < 11) ? (l - mean) : 0.f;
            float var = warp_sum(d * d) * (1.0f / 11.0f);
            float inv = rsqrtf(var + 1e-5f);
            l = d * inv * w1;
            float s1 = fmaxf(warp_sum(l * wl1), 0.0f);
            l = fmaf(s1, wl2, l);
            float mean2 = warp_sum(l) * (1.0f / 11.0f);
            float d2 = (lane < 11) ? (l - mean2) : 0.f;
            float var2 = warp_sum(d2 * d2) * (1.0f / 11.0f);
            float inv2 = rsqrtf(var2 + 1e-5f);
            if (lane < 11) f2s[r * 12 + lane] = d2 * inv2 * w2;
        }
    }
    __syncthreads();

    // ---- kc/vc via A-folding: 10-deep ----
    for (int oid = tid; oid < 704; oid += 128) {
        int h = oid & 31;
        int r = oid >> 5;
        int which = r & 1;
        int j = r >> 1;
        const float* A = which ? sAv : sAk;
        float acc = 0.f;
        #pragma unroll
        for (int p = 0; p < 10; p++) acc = fmaf(f2s[p * 12 + j], A[h * 11 + p], acc);
        (which ? vcs : kcs)[j * 32 + h] = acc;
    }
    __syncthreads();

    // ---- cross-attention (hd=1), no-max softmax ----
    for (int idx = tid; idx < 320; idx += 128) {
        int i = idx >> 5, h = idx & 31;
        float q = sQc[i * 32 + h];
        float den = 0.f, num = 0.f;
        #pragma unroll
        for (int j = 0; j < 11; j++) {
            float e = fast_exp(q * kcs[j * 32 + h]);
            den += e;
            num = fmaf(e, vcs[j * 32 + h], num);
        }
        oas[i * 32 + h] = num / den;
    }
    __syncthreads();

    // ---- CA out projection + residual ----
    for (int idx = tid; idx < 320; idx += 128) {
        int i = idx >> 5, c = idx & 31;
        float acc = 0.f;
        #pragma unroll 8
        for (int hh = 0; hh < 32; hh++)
            acc = fmaf(sWo2[c * 33 + hh], oas[i * 32 + hh], acc);
        y2s[i * 33 + c] = sY1[i * 32 + c] + acc;
    }
    __syncthreads();

    // ---- decoder LN2 + FFN + LN3: warp per row ----
    {
        float w2  = sDln2w[lane];
        float w3  = sDln3w[lane];
        float wl1 = sDlin1[lane];
        float wl2 = sDlin2[lane];
        for (int r = wrp; r < 10; r += 4) {
            float l = y2s[r * 33 + lane];
            float mean = warp_sum(l) * (1.0f / 32.0f);
            float d = l - mean;
            float var = warp_sum(d * d) * (1.0f / 32.0f);
            float inv = rsqrtf(var + 1e-5f);
            l = d * inv * w2;
            float s1 = fmaxf(warp_sum(l * wl1), 0.0f);
            l = fmaf(s1, wl2, l);
            float mean2 = warp_sum(l) * (1.0f / 32.0f);
            float d2 = l - mean2;
            float var2 = warp_sum(d2 * d2) * (1.0f / 32.0f);
            float inv2 = rsqrtf(var2 + 1e-5f);
            y3s[r * 33 + lane] = d2 * inv2 * w3;
        }
    }
    __syncthreads();

    // ---- head: relu(y3 @ Wd0^T) @ Wd1^T ----
    if (tid < 80) {
        int i = tid >> 3, k = tid & 7;
        float acc = 0.f;
        #pragma unroll 8
        for (int c = 0; c < 32; c++) acc = fmaf(sWd0[k * 33 + c], y3s[i * 33 + c], acc);
        hks[i * 8 + k] = fmaxf(acc, 0.0f);
    }
    __syncthreads();
    if (tid < 10) {
        float z = 0.f;
        #pragma unroll
        for (int k = 0; k < 8; k++) z = fmaf(hks[tid * 8 + k], sWd1[k], z);
        out[((n * 10 + tid) * 30 + pi) * 30 + pj] = z;
    }
}

extern "C" void kernel_launch(void* const* d_in, const int* in_sizes, int n_in,
                              void* d_out, int out_size) {
    const float* x       = (const float*)d_in[0];
    const float* Vf      = (const float*)d_in[1];
    const float* enc_in  = (const float*)d_in[2];
    const float* enc_out = (const float*)d_in[3];
    const float* el1     = (const float*)d_in[4];
    const float* el2     = (const float*)d_in[5];
    const float* eln1    = (const float*)d_in[6];
    const float* eln2    = (const float*)d_in[7];
    const float* ffv     = (const float*)d_in[8];
    const float* sa_in   = (const float*)d_in[9];
    const float* sa_out  = (const float*)d_in[10];
    const float* ca_in   = (const float*)d_in[11];
    const float* ca_out  = (const float*)d_in[12];
    const float* dl1     = (const float*)d_in[13];
    const float* dl2     = (const float*)d_in[14];
    const float* dln1    = (const float*)d_in[15];
    const float* dln2    = (const float*)d_in[16];
    const float* dln3    = (const float*)d_in[17];
    const float* wd0     = (const float*)d_in[18];
    const float* wd1     = (const float*)d_in[19];

    precompute_kernel<<<1, 320>>>(Vf, sa_in, sa_out, dln1, ca_in, ffv, enc_in, enc_out);
    gfield_kernel<<<(3 * 16 * 11 * 1024 + 255) / 256, 256>>>(x, enc_in);
    main_kernel<<<14400, 128>>>(x, el1, el2, eln1, eln2, ca_out,
                                dl1, dl2, dln2, dln3, wd0, wd1,
                                (float*)d_out);
}

// round 4
// speedup vs baseline: 1.6306x; 1.4109x over previous
#include <cuda_runtime.h>

// ---------------------------------------------------------------------------
// PixelEachSubstitutor R4:
//  - combined prologue kernel: block 0 = decoder-SA precompute (smem-prefetched),
//    blocks 1.. = G-field builder (bias+scale folded in, + raw-x padded field)
//  - main kernel: 4 pixels / 256-thread block, aliased smem, register-cached
//    inner loops, MUFU exp/div, conflict-free layouts
// ---------------------------------------------------------------------------

#define G_W_SIZE   (3 * 16 * 11 * 1024)      // 540672
#define G_X_SIZE   (16 * 10 * 1024)          // 163840
#define G_TOTAL    (G_W_SIZE + G_X_SIZE)     // 704512
#define SCALE_Q    0.30151134457776363f      // 1/sqrt(11)

__device__ float g_y1[320];    // post-SA+LN1 decoder state (10 x 32)
__device__ float g_qc[320];    // cross-attn queries (10 x 32)
__device__ float g_Ak[352];    // [h*11+p], p=0..8: Wk@ffv9 ; p=9: Wk@S
__device__ float g_Av[352];
__device__ float g_G[G_TOTAL];

__device__ __forceinline__ float fast_exp(float x) {
    float t = x * 1.4426950408889634f;
    t = fmaxf(t, -110.0f);
    float z = t + 12582912.0f;
    int   n = __float_as_int(z) - 0x4B400000;
    float r = t - (z - 12582912.0f);
    float p = 1.3333558e-3f;
    p = fmaf(p, r, 9.6181291e-3f);
    p = fmaf(p, r, 5.5504109e-2f);
    p = fmaf(p, r, 2.4022651e-1f);
    p = fmaf(p, r, 6.9314718e-1f);
    p = fmaf(p, r, 1.0f);
    return __int_as_float((n + 127) << 23) * p;
}

__device__ __forceinline__ float warp_sum(float v) {
    v += __shfl_xor_sync(0xffffffffu, v, 16);
    v += __shfl_xor_sync(0xffffffffu, v, 8);
    v += __shfl_xor_sync(0xffffffffu, v, 4);
    v += __shfl_xor_sync(0xffffffffu, v, 2);
    v += __shfl_xor_sync(0xffffffffu, v, 1);
    return v;
}

// ---------------------------------------------------------------------------
// Prologue kernel. Block 0: decoder precompute. Blocks 1..: G fields.
// 320 threads per block.
// ---------------------------------------------------------------------------
#define P_SAIN 0
#define P_SAOUT 3072
#define P_CAIN 4096
#define P_FFV 7168
#define P_VF 9760
#define P_QS 10080
#define P_KS 10400
#define P_VS 10720
#define P_OS 11040
#define P_RR 11360
#define P_Y1 11680
#define P_SS 12000
#define P_DLN 12032
#define P_SM_SIZE 12096

__global__ void __launch_bounds__(320) prologue_kernel(
    const float* __restrict__ x,        // (16,10,30,30)
    const float* __restrict__ Vf,       // (10,32)
    const float* __restrict__ sa_in,    // (96,32)
    const float* __restrict__ sa_out,   // (32,32)
    const float* __restrict__ dln1,     // (32)
    const float* __restrict__ ca_in,    // (96,32)
    const float* __restrict__ ffv,      // (32,81)
    const float* __restrict__ enc_in,   // (33,11)
    const float* __restrict__ enc_out)  // (11,11)
{
    __shared__ float sm[P_SM_SIZE];
    const int t = threadIdx.x;

    if (blockIdx.x == 0) {
        // ---------------- precompute block ----------------
        // prefetch everything
        for (int i = t; i < 3072; i += 320) sm[P_SAIN + i] = sa_in[i];
        for (int i = t; i < 1024; i += 320) sm[P_SAOUT + i] = sa_out[i];
        for (int i = t; i < 3072; i += 320) sm[P_CAIN + i] = ca_in[i];
        for (int i = t; i < 2592; i += 320) sm[P_FFV + i] = ffv[i];
        for (int i = t; i < 320; i += 320)  sm[P_VF + i] = Vf[i];
        if (t < 32) sm[P_DLN + t] = dln1[t];
        __syncthreads();

        const int i = t >> 5, h = t & 31;

        // ffv tail sums
        if (t < 32) {
            float s = 0.f;
            for (int p = 9; p < 81; p++) s += sm[P_FFV + t * 81 + p];
            sm[P_SS + t] = s;
        }

        // decoder SA qkv (nhead=32, hd=1)
        {
            float aq = 0.f, ak = 0.f, av = 0.f;
            #pragma unroll 8
            for (int v = 0; v < 32; v++) {
                float f = sm[P_VF + i * 32 + v];
                aq = fmaf(sm[P_SAIN + h * 32 + v], f, aq);
                ak = fmaf(sm[P_SAIN + (32 + h) * 32 + v], f, ak);
                av = fmaf(sm[P_SAIN + (64 + h) * 32 + v], f, av);
            }
            sm[P_QS + t] = aq; sm[P_KS + t] = ak; sm[P_VS + t] = av;
        }
        __syncthreads();

        {
            float qv = sm[P_QS + i * 32 + h];
            float m = -1e30f;
            #pragma unroll
            for (int j = 0; j < 10; j++) m = fmaxf(m, qv * sm[P_KS + j * 32 + h]);
            float den = 0.f, num = 0.f;
            #pragma unroll
            for (int j = 0; j < 10; j++) {
                float e = fast_exp(fmaf(qv, sm[P_KS + j * 32 + h], -m));
                den += e;
                num = fmaf(e, sm[P_VS + j * 32 + h], num);
            }
            sm[P_OS + t] = __fdividef(num, den);
        }
        __syncthreads();

        {
            float acc = 0.f;
            #pragma unroll 8
            for (int hh = 0; hh < 32; hh++)
                acc = fmaf(sm[P_SAOUT + h * 32 + hh], sm[P_OS + i * 32 + hh], acc);
            sm[P_RR + t] = sm[P_VF + i * 32 + h] + acc;
        }
        __syncthreads();

        if (t < 10) {
            float mean = 0.f;
            for (int c = 0; c < 32; c++) mean += sm[P_RR + t * 32 + c];
            mean *= (1.0f / 32.0f);
            float var = 0.f;
            for (int c = 0; c < 32; c++) { float d = sm[P_RR + t * 32 + c] - mean; var = fmaf(d, d, var); }
            var *= (1.0f / 32.0f);
            float inv = rsqrtf(var + 1e-5f);
            for (int c = 0; c < 32; c++) {
                float yv = (sm[P_RR + t * 32 + c] - mean) * inv * sm[P_DLN + c];
                sm[P_Y1 + t * 32 + c] = yv;
                g_y1[t * 32 + c] = yv;
            }
        }
        __syncthreads();

        // cross-attn queries
        {
            float acc = 0.f;
            #pragma unroll 8
            for (int v = 0; v < 32; v++)
                acc = fmaf(sm[P_CAIN + h * 32 + v], sm[P_Y1 + i * 32 + v], acc);
            g_qc[t] = acc;
        }
        // A_k / A_v folding
        {
            int hh = t / 10, p = t % 10;
            float accK = 0.f, accV = 0.f;
            #pragma unroll 8
            for (int v = 0; v < 32; v++) {
                float fv = (p < 9) ? sm[P_FFV + v * 81 + p] : sm[P_SS + v];
                accK = fmaf(sm[P_CAIN + (32 + hh) * 32 + v], fv, accK);
                accV = fmaf(sm[P_CAIN + (64 + hh) * 32 + v], fv, accV);
            }
            g_Ak[hh * 11 + p] = accK;
            g_Av[hh * 11 + p] = accV;
        }
    } else {
        // ---------------- G-field block ----------------
        // local M = enc_out @ Wv[:, :10], bvp = enc_out @ Wv[:,10]
        float* M   = sm;        // 110
        float* bvp = sm + 112;  // 11
        if (t < 110) {
            int c = t / 10, cp = t % 10;
            float acc = 0.f;
            #pragma unroll
            for (int a = 0; a < 11; a++)
                acc = fmaf(enc_out[c * 11 + a], enc_in[(22 + a) * 11 + cp], acc);
            M[t] = acc;
        }
        if (t < 11) {
            float acc = 0.f;
            #pragma unroll
            for (int a = 0; a < 11; a++)
                acc = fmaf(enc_out[t * 11 + a], enc_in[(22 + a) * 11 + 10], acc);
            bvp[t] = acc;
        }
        __syncthreads();

        int g = (blockIdx.x - 1) * 320 + t;
        if (g >= G_TOTAL) return;

        int cell = g & 1023;
        int jj = cell & 31;
        int ii = cell >> 5;
        bool interior = (ii >= 1 && ii <= 30 && jj >= 1 && jj <= 30);

        float val;
        if (g < G_W_SIZE) {
            int u = g >> 10;            // 0..527
            int a = u % 11;
            int q = u / 11;
            int n = q & 15;
            int w = q >> 4;
            float bias, acc = 0.f;
            if (w == 0)      bias = __ldg(enc_in + a * 11 + 10);
            else if (w == 1) bias = __ldg(enc_in + (11 + a) * 11 + 10);
            else             bias = bvp[a];
            if (interior) {
                const float* xr = x + (n * 10) * 900 + (ii - 1) * 30 + (jj - 1);
                if (w == 0) {
                    #pragma unroll
                    for (int c = 0; c < 10; c++) acc = fmaf(__ldg(enc_in + a * 11 + c), xr[c * 900], acc);
                } else if (w == 1) {
                    #pragma unroll
                    for (int c = 0; c < 10; c++) acc = fmaf(__ldg(enc_in + (11 + a) * 11 + c), xr[c * 900], acc);
                } else {
                    #pragma unroll
                    for (int c = 0; c < 10; c++) acc = fmaf(M[a * 10 + c], xr[c * 900], acc);
                }
            }
            val = acc + bias;
            if (w == 0) val *= SCALE_Q;
        } else {
            int t2 = g - G_W_SIZE;
            int u = t2 >> 10;           // n*10+c
            val = interior ? __ldg(x + u * 900 + (ii - 1) * 30 + (jj - 1)) : 0.0f;
        }
        g_G[g] = val;
    }
}

// ---------------------------------------------------------------------------
// Main kernel: 4 pixels per 256-thread block, 3600 blocks.
// Per-pixel activation buffer (1312 floats), aliased across phases:
//   phase A: q9@0(108) k9@108 vp9@216 f9@324 scs@432 ggs@540(120) invd@660(12)
//   phase B: f2T@0(132)  [c*12+p]
//   phase C: kcs@160(416) vcs@576(416)  [h*13+j]
//   phase D: oas@992(320) [i*32+h]
//   phase E: y2/y3@0(330) [i*33+c],  hks@340(80)
// ---------------------------------------------------------------------------
#define ACT 1312
#define OQ9 0
#define OK9 108
#define OVP 216
#define OF9 324
#define OSC 432
#define OGG 540
#define OINV 660
#define OF2 0
#define OKC 160
#define OVC 576
#define OOA 992
#define OY2 0
#define OHK 340

__global__ void __launch_bounds__(256, 4) main_kernel(
    const float* __restrict__ el1, const float* __restrict__ el2,
    const float* __restrict__ eln1, const float* __restrict__ eln2,
    const float* __restrict__ ca_out,
    const float* __restrict__ dl1, const float* __restrict__ dl2,
    const float* __restrict__ dln2, const float* __restrict__ dln3,
    const float* __restrict__ wd0, const float* __restrict__ wd1,
    float* __restrict__ out)
{
    __shared__ float sAk[352], sAv[352];     // [h*11+p]
    __shared__ float sWo2[1056];             // [c*33+h]
    __shared__ float sQc[320], sY1[320];     // [i*32+h]
    __shared__ float sDlin1[32], sDlin2[32], sDln2w[32], sDln3w[32];
    __shared__ float sWd0[264];              // [k*33+c]
    __shared__ float sWd1[8];
    __shared__ float sLin1[11], sLin2[11], sLn1[11], sLn2[11];
    __shared__ __align__(16) float act[4 * ACT];
    __shared__ int spn[4], sppi[4], sppj[4];

    const int tid = threadIdx.x;
    const int lane = tid & 31;
    const int wrp  = tid >> 5;

    // ---- stage weights + pixel coords ----
    for (int t = tid; t < 352; t += 256) { sAk[t] = g_Ak[t]; sAv[t] = g_Av[t]; }
    for (int t = tid; t < 1024; t += 256) sWo2[(t >> 5) * 33 + (t & 31)] = ca_out[t];
    for (int t = tid; t < 320; t += 256) { sQc[t] = g_qc[t]; sY1[t] = g_y1[t]; }
    if (tid < 32) {
        sDlin1[tid] = dl1[tid]; sDlin2[tid] = dl2[tid];
        sDln2w[tid] = dln2[tid]; sDln3w[tid] = dln3[tid];
    }
    for (int t = tid; t < 256; t += 256) sWd0[(t >> 5) * 33 + (t & 31)] = wd0[t];
    if (tid < 8) sWd1[tid] = wd1[tid];
    if (tid < 11) {
        sLin1[tid] = el1[tid]; sLin2[tid] = el2[tid];
        sLn1[tid] = eln1[tid]; sLn2[tid] = eln2[tid];
    }
    if (tid < 4) {
        int pixel = blockIdx.x * 4 + tid;
        int n = pixel / 900, rem = pixel % 900;
        spn[tid] = n; sppi[tid] = rem / 30; sppj[tid] = rem % 30;
    }
    __syncthreads();

    // ---- gather: q9/k9/vp9 from G fields (pre-biased/scaled), f9 from x field ----
    for (int t = tid; t < 1584; t += 256) {
        int px = t / 396, r = t % 396;
        int w = r / 99, rr = r % 99;
        int p = rr / 11, a = rr % 11;
        int cell = (sppi[px] + p / 3) * 32 + sppj[px] + p % 3;
        int n = spn[px];
        float v;
        int dst;
        if (w < 3) {
            v = g_G[((w * 16 + n) * 11 + a) * 1024 + cell];
            dst = (w == 0) ? OQ9 : (w == 1) ? OK9 : OVP;
        } else {
            v = (a < 10) ? g_G[G_W_SIZE + (n * 10 + a) * 1024 + cell] : 1.0f;
            dst = OF9;
        }
        act[px * ACT + dst + p * 12 + a] = v;
    }
    __syncthreads();

    // ---- 9x9 encoder scores (scale pre-folded into q) ----
    for (int idx = tid; idx < 324; idx += 256) {
        int px = idx / 81, r = idx % 81;
        int i = r / 9, j = r % 9;
        const float* q = &act[px * ACT + OQ9 + i * 12];
        const float* k = &act[px * ACT + OK9 + j * 12];
        float acc = 0.f;
        #pragma unroll
        for (int a = 0; a < 11; a++) acc = fmaf(q[a], k[a], acc);
        act[px * ACT + OSC + i * 12 + j] = acc;
    }
    __syncthreads();

    // ---- row softmax with +72 zero-key correction ----
    if (tid < 36) {
        int px = tid / 9, i = tid % 9;
        float* sc = &act[px * ACT + OSC + i * 12];
        float m = 0.0f;
        #pragma unroll
        for (int j = 0; j < 9; j++) m = fmaxf(m, sc[j]);
        float sum = 72.0f * fast_exp(-m);
        #pragma unroll
        for (int j = 0; j < 9; j++) {
            float e = fast_exp(sc[j] - m);
            sc[j] = e;
            sum += e;
        }
        act[px * ACT + OINV + i] = __fdividef(1.0f, sum);
    }
    __syncthreads();

    // ---- attn @ vp + residual; row 9 uniform ----
    for (int idx = tid; idx < 440; idx += 256) {
        int px = idx / 110, r = idx % 110;
        float* pb = &act[px * ACT];
        if (r < 99) {
            int i = r / 11, c = r % 11;
            float acc = 0.f;
            #pragma unroll
            for (int j = 0; j < 9; j++) acc = fmaf(pb[OSC + i * 12 + j], pb[OVP + j * 12 + c], acc);
            pb[OGG + i * 12 + c] = fmaf(acc, pb[OINV + i], pb[OF9 + i * 12 + c]);
        } else {
            int c = r - 99;
            float s = 0.f;
            #pragma unroll
            for (int j = 0; j < 9; j++) s += pb[OVP + j * 12 + c];
            pb[OGG + 108 + c] = s * (1.0f / 81.0f);
        }
    }
    __syncthreads();

    // ---- encoder LN1 + FFN + LN2 -> f2T[c*12+p]: warp per row ----
    {
        float w1  = (lane < 11) ? sLn1[lane]  : 0.f;
        float w2  = (lane < 11) ? sLn2[lane]  : 0.f;
        float wl1 = (lane < 11) ? sLin1[lane] : 0.f;
        float wl2 = (lane < 11) ? sLin2[lane] : 0.f;
        for (int r = wrp; r < 40; r += 8) {
            int px = r / 10, row = r % 10;
            float* pb = &act[px * ACT];
            float l = (lane < 11) ? pb[OGG + row * 12 + lane] : 0.f;
            float mean = warp_sum(l) * (1.0f / 11.0f);
            float d = (lane < 11) ? (l - mean) : 0.f;
            float var = warp_sum(d * d) * (1.0f / 11.0f);
            float inv = rsqrtf(var + 1e-5f);
            l = d * inv * w1;
            float s1 = fmaxf(warp_sum(l * wl1), 0.0f);
            l = fmaf(s1, wl2, l);
            float mean2 = warp_sum(l) * (1.0f / 11.0f);
            float d2 = (lane < 11) ? (l - mean2) : 0.f;
            float var2 = warp_sum(d2 * d2) * (1.0f / 11.0f);
            float inv2 = rsqrtf(var2 + 1e-5f);
            if (lane < 11) pb[OF2 + lane * 12 + row] = d2 * inv2 * w2;
        }
    }
    __syncthreads();

    // ---- kc/vc: thread = (px, which, h); A row cached; f2T broadcast ----
    {
        int h = tid & 31, which = (tid >> 5) & 1, px = tid >> 6;
        const float* A = which ? sAv : sAk;
        float* pb = &act[px * ACT];
        float a[10];
        #pragma unroll
        for (int p = 0; p < 10; p++) a[p] = A[h * 11 + p];
        float* dst = pb + (which ? OVC : OKC);
        #pragma unroll
        for (int j = 0; j < 11; j++) {
            const float* f2 = pb + OF2 + j * 12;
            float acc = 0.f;
            #pragma unroll
            for (int p = 0; p < 10; p++) acc = fmaf(f2[p], a[p], acc);
            dst[h * 13 + j] = acc;
        }
    }
    __syncthreads();

    // ---- cross-attention (hd=1): thread = (px, ih, h); kc/vc cached ----
    {
        int h = lane, px = wrp & 3, ih = wrp >> 2;
        float* pb = &act[px * ACT];
        float kk[11], vv[11];
        #pragma unroll
        for (int j = 0; j < 11; j++) {
            kk[j] = pb[OKC + h * 13 + j];
            vv[j] = pb[OVC + h * 13 + j];
        }
        #pragma unroll
        for (int k = 0; k < 5; k++) {
            int i = ih * 5 + k;
            float q = sQc[i * 32 + h];
            float den = 0.f, num = 0.f;
            #pragma unroll
            for (int j = 0; j < 11; j++) {
                float e = __expf(q * kk[j]);
                den += e;
                num = fmaf(e, vv[j], num);
            }
            pb[OOA + i * 32 + h] = __fdividef(num, den);
        }
    }
    __syncthreads();

    // ---- CA out projection + residual: thread = (px, ih, c); Wo2 row cached ----
    {
        int c = lane, px = wrp & 3, ih = wrp >> 2;
        float* pb = &act[px * ACT];
        float w[32];
        #pragma unroll
        for (int hh = 0; hh < 32; hh++) w[hh] = sWo2[c * 33 + hh];
        #pragma unroll
        for (int k = 0; k < 5; k++) {
            int i = ih * 5 + k;
            const float4* o4 = (const float4*)&pb[OOA + i * 32];
            float acc = 0.f;
            #pragma unroll
            for (int q4 = 0; q4 < 8; q4++) {
                float4 m4 = o4[q4];
                acc = fmaf(w[4 * q4 + 0], m4.x, acc);
                acc = fmaf(w[4 * q4 + 1], m4.y, acc);
                acc = fmaf(w[4 * q4 + 2], m4.z, acc);
                acc = fmaf(w[4 * q4 + 3], m4.w, acc);
            }
            pb[OY2 + i * 33 + c] = sY1[i * 32 + c] + acc;
        }
    }
    __syncthreads();

    // ---- decoder LN2 + FFN + LN3 in place: warp per row ----
    {
        float w2  = sDln2w[lane];
        float w3  = sDln3w[lane];
        float wl1 = sDlin1[lane];
        float wl2 = sDlin2[lane];
        for (int r = wrp; r < 40; r += 8) {
            int px = r / 10, i = r % 10;
            float* row = &act[px * ACT + OY2 + i * 33];
            float l = row[lane];
            float mean = warp_sum(l) * (1.0f / 32.0f);
            float d = l - mean;
            float var = warp_sum(d * d) * (1.0f / 32.0f);
            float inv = rsqrtf(var + 1e-5f);
            l = d * inv * w2;
            float s1 = fmaxf(warp_sum(l * wl1), 0.0f);
            l = fmaf(s1, wl2, l);
            float mean2 = warp_sum(l) * (1.0f / 32.0f);
            float d2 = l - mean2;
            float var2 = warp_sum(d2 * d2) * (1.0f / 32.0f);
            float inv2 = rsqrtf(var2 + 1e-5f);
            row[lane] = d2 * inv2 * w3;
        }
    }
    __syncthreads();

    // ---- head: relu(y3 @ Wd0^T) ----
    for (int idx = tid; idx < 320; idx += 256) {
        int px = idx / 80, r = idx % 80;
        int i = r >> 3, k = r & 7;
        float* pb = &act[px * ACT];
        float acc = 0.f;
        #pragma unroll 8
        for (int c = 0; c < 32; c++) acc = fmaf(sWd0[k * 33 + c], pb[OY2 + i * 33 + c], acc);
        pb[OHK + i * 8 + k] = fmaxf(acc, 0.0f);
    }
    __syncthreads();

    // ---- final 1x8 dot + output ----
    if (tid < 40) {
        int px = tid / 10, c = tid % 10;
        float* pb = &act[px * ACT];
        float z = 0.f;
        #pragma unroll
        for (int k = 0; k < 8; k++) z = fmaf(pb[OHK + c * 8 + k], sWd1[k], z);
        out[((spn[px] * 10 + c) * 30 + sppi[px]) * 30 + sppj[px]] = z;
    }
}

extern "C" void kernel_launch(void* const* d_in, const int* in_sizes, int n_in,
                              void* d_out, int out_size) {
    const float* x       = (const float*)d_in[0];
    const float* Vf      = (const float*)d_in[1];
    const float* enc_in  = (const float*)d_in[2];
    const float* enc_out = (const float*)d_in[3];
    const float* el1     = (const float*)d_in[4];
    const float* el2     = (const float*)d_in[5];
    const float* eln1    = (const float*)d_in[6];
    const float* eln2    = (const float*)d_in[7];
    const float* ffv     = (const float*)d_in[8];
    const float* sa_in   = (const float*)d_in[9];
    const float* sa_out  = (const float*)d_in[10];
    const float* ca_in   = (const float*)d_in[11];
    const float* ca_out  = (const float*)d_in[12];
    const float* dl1     = (const float*)d_in[13];
    const float* dl2     = (const float*)d_in[14];
    const float* dln1    = (const float*)d_in[15];
    const float* dln2    = (const float*)d_in[16];
    const float* dln3    = (const float*)d_in[17];
    const float* wd0     = (const float*)d_in[18];
    const float* wd1     = (const float*)d_in[19];

    int gblocks = 1 + (G_TOTAL + 319) / 320;
    prologue_kernel<<<gblocks, 320>>>(x, Vf, sa_in, sa_out, dln1, ca_in, ffv,
                                      enc_in, enc_out);
    main_kernel<<<3600, 256>>>(el1, el2, eln1, eln2, ca_out,
                               dl1, dl2, dln2, dln3, wd0, wd1,
                               (float*)d_out);
}

// round 5
// speedup vs baseline: 1.8534x; 1.1367x over previous
#include <cuda_runtime.h>

// ---------------------------------------------------------------------------
// PixelEachSubstitutor R5:
//  - E-field: encoder attention exp(scores) precomputed per (cell, rel-offset)
//    -> scores GEMM + softmax exp leave the pixel loop entirely
//  - all fields in [cell][32] layout: coalesced warp gathers, shift-only indexing
//  - 16-lane dual-row encoder LN, conflict-free stride-17/13 smem layouts
// ---------------------------------------------------------------------------

#define SCALE_Q 0.30151134457776363f   // 1/sqrt(11)
#define ACT 1360                        // per-pixel act floats (mod 32 == 16)

__device__ float g_y1[320];
__device__ float g_qc[320];
__device__ float g_Ak[352];   // [h*11+p]
__device__ float g_Av[352];
__device__ __align__(16) float g_QK[16 * 1024 * 32];  // [n*1024+cell][32]: q(scaled) 0..15, k 16..31
__device__ __align__(16) float g_G2[16 * 1024 * 32];  // vp 0..15, x-raw 16..31
__device__ __align__(16) float g_E [16 * 1024 * 32];  // exp(q.k) at rel slots 0..24

__constant__ int c_cell9[9] = {0, 1, 2, 32, 33, 34, 64, 65, 66};
__constant__ int c_rel144[144] = {
    12,13,14,17,18,19,22,23,24, 0,0,0,0,0,0,0,
    11,12,13,16,17,18,21,22,23, 0,0,0,0,0,0,0,
    10,11,12,15,16,17,20,21,22, 0,0,0,0,0,0,0,
     7, 8, 9,12,13,14,17,18,19, 0,0,0,0,0,0,0,
     6, 7, 8,11,12,13,16,17,18, 0,0,0,0,0,0,0,
     5, 6, 7,10,11,12,15,16,17, 0,0,0,0,0,0,0,
     2, 3, 4, 7, 8, 9,12,13,14, 0,0,0,0,0,0,0,
     1, 2, 3, 6, 7, 8,11,12,13, 0,0,0,0,0,0,0,
     0, 1, 2, 5, 6, 7,10,11,12, 0,0,0,0,0,0,0
};

__device__ __forceinline__ float fast_exp(float x) {
    float t = x * 1.4426950408889634f;
    t = fmaxf(t, -110.0f);
    float z = t + 12582912.0f;
    int   n = __float_as_int(z) - 0x4B400000;
    float r = t - (z - 12582912.0f);
    float p = 1.3333558e-3f;
    p = fmaf(p, r, 9.6181291e-3f);
    p = fmaf(p, r, 5.5504109e-2f);
    p = fmaf(p, r, 2.4022651e-1f);
    p = fmaf(p, r, 6.9314718e-1f);
    p = fmaf(p, r, 1.0f);
    return __int_as_float((n + 127) << 23) * p;
}

__device__ __forceinline__ float warp_sum(float v) {
    v += __shfl_xor_sync(0xffffffffu, v, 16);
    v += __shfl_xor_sync(0xffffffffu, v, 8);
    v += __shfl_xor_sync(0xffffffffu, v, 4);
    v += __shfl_xor_sync(0xffffffffu, v, 2);
    v += __shfl_xor_sync(0xffffffffu, v, 1);
    return v;
}
__device__ __forceinline__ float warp_sum16(float v) {
    v += __shfl_xor_sync(0xffffffffu, v, 8);
    v += __shfl_xor_sync(0xffffffffu, v, 4);
    v += __shfl_xor_sync(0xffffffffu, v, 2);
    v += __shfl_xor_sync(0xffffffffu, v, 1);
    return v;
}

// ---------------------------------------------------------------------------
// Prologue A. Block 0: decoder precompute. Blocks 1..: QK + G2 fields.
// ---------------------------------------------------------------------------
#define P_SAIN 0
#define P_SAOUT 3072
#define P_CAIN 4096
#define P_FFV 7168
#define P_VF 9760
#define P_QS 10080
#define P_KS 10400
#define P_VS 10720
#define P_OS 11040
#define P_RR 11360
#define P_Y1 11680
#define P_SS 12000
#define P_DLN 12032
#define P_SM_SIZE 12096

__global__ void __launch_bounds__(320) prologueA_kernel(
    const float* __restrict__ x,
    const float* __restrict__ Vf,
    const float* __restrict__ sa_in,
    const float* __restrict__ sa_out,
    const float* __restrict__ dln1,
    const float* __restrict__ ca_in,
    const float* __restrict__ ffv,
    const float* __restrict__ enc_in,
    const float* __restrict__ enc_out)
{
    __shared__ float sm[P_SM_SIZE];
    const int t = threadIdx.x;

    if (blockIdx.x == 0) {
        for (int i = t; i < 3072; i += 320) sm[P_SAIN + i] = sa_in[i];
        for (int i = t; i < 1024; i += 320) sm[P_SAOUT + i] = sa_out[i];
        for (int i = t; i < 3072; i += 320) sm[P_CAIN + i] = ca_in[i];
        for (int i = t; i < 2592; i += 320) sm[P_FFV + i] = ffv[i];
        if (t < 320) sm[P_VF + t] = Vf[t];
        if (t < 32) sm[P_DLN + t] = dln1[t];
        __syncthreads();

        const int i = t >> 5, h = t & 31;
        if (t < 32) {
            float s = 0.f;
            for (int p = 9; p < 81; p++) s += sm[P_FFV + t * 81 + p];
            sm[P_SS + t] = s;
        }
        {
            float aq = 0.f, ak = 0.f, av = 0.f;
            #pragma unroll 8
            for (int v = 0; v < 32; v++) {
                float f = sm[P_VF + i * 32 + v];
                aq = fmaf(sm[P_SAIN + h * 32 + v], f, aq);
                ak = fmaf(sm[P_SAIN + (32 + h) * 32 + v], f, ak);
                av = fmaf(sm[P_SAIN + (64 + h) * 32 + v], f, av);
            }
            sm[P_QS + t] = aq; sm[P_KS + t] = ak; sm[P_VS + t] = av;
        }
        __syncthreads();
        {
            float qv = sm[P_QS + i * 32 + h];
            float m = -1e30f;
            #pragma unroll
            for (int j = 0; j < 10; j++) m = fmaxf(m, qv * sm[P_KS + j * 32 + h]);
            float den = 0.f, num = 0.f;
            #pragma unroll
            for (int j = 0; j < 10; j++) {
                float e = fast_exp(fmaf(qv, sm[P_KS + j * 32 + h], -m));
                den += e;
                num = fmaf(e, sm[P_VS + j * 32 + h], num);
            }
            sm[P_OS + t] = __fdividef(num, den);
        }
        __syncthreads();
        {
            float acc = 0.f;
            #pragma unroll 8
            for (int hh = 0; hh < 32; hh++)
                acc = fmaf(sm[P_SAOUT + h * 32 + hh], sm[P_OS + i * 32 + hh], acc);
            sm[P_RR + t] = sm[P_VF + i * 32 + h] + acc;
        }
        __syncthreads();
        if (t < 10) {
            float mean = 0.f;
            for (int c = 0; c < 32; c++) mean += sm[P_RR + t * 32 + c];
            mean *= (1.0f / 32.0f);
            float var = 0.f;
            for (int c = 0; c < 32; c++) { float d = sm[P_RR + t * 32 + c] - mean; var = fmaf(d, d, var); }
            var *= (1.0f / 32.0f);
            float inv = rsqrtf(var + 1e-5f);
            for (int c = 0; c < 32; c++) {
                float yv = (sm[P_RR + t * 32 + c] - mean) * inv * sm[P_DLN + c];
                sm[P_Y1 + t * 32 + c] = yv;
                g_y1[t * 32 + c] = yv;
            }
        }
        __syncthreads();
        {
            float acc = 0.f;
            #pragma unroll 8
            for (int v = 0; v < 32; v++)
                acc = fmaf(sm[P_CAIN + h * 32 + v], sm[P_Y1 + i * 32 + v], acc);
            g_qc[t] = acc;
        }
        {
            int hh = t / 10, p = t % 10;
            float accK = 0.f, accV = 0.f;
            #pragma unroll 8
            for (int v = 0; v < 32; v++) {
                float fv = (p < 9) ? sm[P_FFV + v * 81 + p] : sm[P_SS + v];
                accK = fmaf(sm[P_CAIN + (32 + hh) * 32 + v], fv, accK);
                accV = fmaf(sm[P_CAIN + (64 + hh) * 32 + v], fv, accV);
            }
            g_Ak[hh * 11 + p] = accK;
            g_Av[hh * 11 + p] = accV;
        }
    } else {
        // field builder: M = enc_out @ Wv[:, :10], bvp = enc_out @ Wv[:,10]
        float* M   = sm;        // 110
        float* bvp = sm + 112;  // 11
        if (t < 110) {
            int c = t / 10, cp = t % 10;
            float acc = 0.f;
            #pragma unroll
            for (int a = 0; a < 11; a++)
                acc = fmaf(enc_out[c * 11 + a], enc_in[(22 + a) * 11 + cp], acc);
            M[t] = acc;
        }
        if (t < 11) {
            float acc = 0.f;
            #pragma unroll
            for (int a = 0; a < 11; a++)
                acc = fmaf(enc_out[t * 11 + a], enc_in[(22 + a) * 11 + 10], acc);
            bvp[t] = acc;
        }
        __syncthreads();

        int g = (blockIdx.x - 1) * 320 + t;
        if (g >= (1 << 20)) return;
        int slot = g & 31;
        int cell = (g >> 5) & 1023;
        int n    = (g >> 15) & 15;
        int fld  = g >> 19;          // 0 = QK, 1 = G2
        int jj = cell & 31, ii = cell >> 5;
        bool interior = (ii >= 1 && ii <= 30 && jj >= 1 && jj <= 30);
        const float* xr = x + n * 9000 + (ii - 1) * 30 + (jj - 1);

        int a = slot & 15;
        int hi = slot >> 4;
        float val = 0.f;
        if (fld == 0) {
            if (a <= 10) {
                int row = hi ? (11 + a) : a;
                float acc = __ldg(enc_in + row * 11 + 10);  // ones-channel bias
                if (interior) {
                    #pragma unroll
                    for (int c = 0; c < 10; c++)
                        acc = fmaf(__ldg(enc_in + row * 11 + c), xr[c * 900], acc);
                }
                val = hi ? acc : acc * SCALE_Q;
            }
        } else {
            if (hi == 0) {
                if (a <= 10) {
                    float acc = bvp[a];
                    if (interior) {
                        #pragma unroll
                        for (int c = 0; c < 10; c++)
                            acc = fmaf(M[a * 10 + c], xr[c * 900], acc);
                    }
                    val = acc;
                }
            } else {
                if (a < 10)       val = interior ? xr[a * 900] : 0.0f;
                else if (a == 10) val = 1.0f;
            }
        }
        (fld == 0 ? g_QK : g_G2)[(((n << 10) | cell) << 5) | slot] = val;
    }
}

// ---------------------------------------------------------------------------
// Prologue B: E-field = exp(q(cellA) . k(cellA+rel)) for rel in 5x5.
// ---------------------------------------------------------------------------
__global__ void __launch_bounds__(256) prologueB_kernel()
{
    int t = blockIdx.x * 256 + threadIdx.x;
    if (t >= (1 << 19)) return;
    int slot = t & 31;
    int cellA = (t >> 5) & 1023;
    int n = t >> 15;

    float val = 0.f;
    if (slot < 25) {
        int ra = slot / 5, rb = slot - ra * 5;
        int rA = (cellA >> 5) + ra - 2;
        int cB = (cellA & 31) + rb - 2;
        if (rA >= 0 && rA <= 31 && cB >= 0 && cB <= 31) {
            const float4* Q = (const float4*)&g_QK[(t - slot)];
            const float4* K = (const float4*)&g_QK[(((n << 10) | (rA * 32 + cB)) << 5) | 16];
            float acc = 0.f;
            #pragma unroll
            for (int u = 0; u < 3; u++) {
                float4 q4 = Q[u], k4 = K[u];
                acc = fmaf(q4.x, k4.x, acc);
                acc = fmaf(q4.y, k4.y, acc);
                acc = fmaf(q4.z, k4.z, acc);
                acc = fmaf(q4.w, k4.w, acc);
            }
            val = __expf(acc);
        }
    }
    g_E[t] = val;
}

// ---------------------------------------------------------------------------
// Main kernel: 4 pixels / 256-thread block, 3600 blocks.
// act aliasing (per pixel, ACT=1360 floats):
//  OSC 0(144) OVP 144(144) OF9 288(144) OINV 432(16) OGG 448(160)
//  OF2 0(192,[c*17+p]) OKC 192(416,[h*13+c]) OVC 608(416) OOA 1024(320)
//  OY2 0(330) OHK 336(80)
// ---------------------------------------------------------------------------
#define OSC 0
#define OVP 144
#define OF9 288
#define OINV 432
#define OGG 448
#define OF2 0
#define OKC 192
#define OVC 608
#define OOA 1024
#define OY2 0
#define OHK 336

__global__ void __launch_bounds__(256, 4) main_kernel(
    const float* __restrict__ el1, const float* __restrict__ el2,
    const float* __restrict__ eln1, const float* __restrict__ eln2,
    const float* __restrict__ ca_out,
    const float* __restrict__ dl1, const float* __restrict__ dl2,
    const float* __restrict__ dln2, const float* __restrict__ dln3,
    const float* __restrict__ wd0, const float* __restrict__ wd1,
    float* __restrict__ out)
{
    __shared__ float sAk[352], sAv[352];
    __shared__ float sWo2[1056];
    __shared__ float sQc[320], sY1[320];
    __shared__ float sDlin1[32], sDlin2[32], sDln2w[32], sDln3w[32];
    __shared__ float sWd0[264], sWd1[8];
    __shared__ float sLin1[11], sLin2[11], sLn1[11], sLn2[11];
    __shared__ __align__(16) float act[4 * ACT];
    __shared__ int spn[4], sppi[4], sppj[4], sppc[4];

    const int tid = threadIdx.x;
    const int lane = tid & 31;
    const int wrp  = tid >> 5;

    for (int t = tid; t < 352; t += 256) { sAk[t] = g_Ak[t]; sAv[t] = g_Av[t]; }
    for (int t = tid; t < 1024; t += 256) sWo2[(t >> 5) * 33 + (t & 31)] = ca_out[t];
    for (int t = tid; t < 320; t += 256) { sQc[t] = g_qc[t]; sY1[t] = g_y1[t]; }
    if (tid < 32) {
        sDlin1[tid] = dl1[tid]; sDlin2[tid] = dl2[tid];
        sDln2w[tid] = dln2[tid]; sDln3w[tid] = dln3[tid];
    }
    if (tid < 256) { int t = tid; sWd0[(t >> 5) * 33 + (t & 31)] = wd0[t]; }
    if (tid < 8) sWd1[tid] = wd1[tid];
    if (tid < 11) {
        sLin1[tid] = el1[tid]; sLin2[tid] = el2[tid];
        sLn1[tid] = eln1[tid]; sLn2[tid] = eln2[tid];
    }
    if (tid < 4) {
        int pixel = blockIdx.x * 4 + tid;
        int n = pixel / 900, rem = pixel % 900;
        int pi = rem / 30, pj = rem % 30;
        spn[tid] = n; sppi[tid] = pi; sppj[tid] = pj;
        sppc[tid] = pi * 32 + pj;
    }
    __syncthreads();

    // ---- gather vp + f9 from G2 (coalesced 128B per warp) ----
    {
        int px = tid >> 6, t64 = tid & 63;
        int base = (spn[px] << 10) | sppc[px];
        float* pb = &act[px * ACT];
        #pragma unroll
        for (int it = 0; it < 5; it++) {
            int r = it * 64 + t64;
            if (r < 288) {
                int cellIdx = r >> 5, slot = r & 31;
                float v = g_G2[((base + c_cell9[cellIdx]) << 5) | slot];
                pb[OVP + (slot >> 4) * 144 + (cellIdx << 4) + (slot & 15)] = v;
            }
        }
    }
    // ---- gather E (81 per pixel) ----
    for (int t = tid; t < 576; t += 256) {
        int i = t >> 6, px = (t >> 4) & 3, j = t & 15;
        if (j < 9) {
            int base = (spn[px] << 10) | (sppc[px] + c_cell9[i]);
            act[px * ACT + OSC + (i << 4) + j] =
                __ldg(&g_E[(base << 5) | c_rel144[(i << 4) + j]]);
        }
    }
    __syncthreads();

    // ---- row denominators: den = 72 + sum(E) ----
    if (tid < 64) {
        int px = tid >> 4, i = tid & 15;
        if (i < 9) {
            float* pb = &act[px * ACT];
            float s = 72.0f;
            #pragma unroll
            for (int j = 0; j < 9; j++) s += pb[OSC + (i << 4) + j];
            pb[OINV + i] = __fdividef(1.0f, s);
        }
    }
    __syncthreads();

    // ---- attn @ vp + residual -> ggs; row 9 uniform ----
    for (int t = tid; t < 640; t += 256) {
        int i = t >> 6, px = (t >> 4) & 3, a = t & 15;
        if (a < 11) {
            float* pb = &act[px * ACT];
            if (i < 9) {
                float acc = 0.f;
                #pragma unroll
                for (int j = 0; j < 9; j++)
                    acc = fmaf(pb[OSC + (i << 4) + j], pb[OVP + (j << 4) + a], acc);
                pb[OGG + (i << 4) + a] = fmaf(acc, pb[OINV + i], pb[OF9 + (i << 4) + a]);
            } else {
                float s = 0.f;
                #pragma unroll
                for (int j = 0; j < 9; j++) s += pb[OVP + (j << 4) + a];
                pb[OGG + 144 + a] = s * (1.0f / 81.0f);
            }
        }
    }
    __syncthreads();

    // ---- encoder LN1 + FFN + LN2 -> f2T[c*17+p]; 2 rows per warp (16 lanes) ----
    {
        int c = lane & 15;
        bool on = (c < 11);
        float w1  = on ? sLn1[c]  : 0.f;
        float w2  = on ? sLn2[c]  : 0.f;
        float wl1 = on ? sLin1[c] : 0.f;
        float wl2 = on ? sLin2[c] : 0.f;
        for (int rp = wrp; rp < 20; rp += 8) {
            int px = rp / 5, pr = rp % 5;
            int row = pr * 2 + (lane >> 4);
            float* pb = &act[px * ACT];
            float l = on ? pb[OGG + (row << 4) + c] : 0.f;
            float mean = warp_sum16(l) * (1.0f / 11.0f);
            float d = on ? (l - mean) : 0.f;
            float var = warp_sum16(d * d) * (1.0f / 11.0f);
            float inv = rsqrtf(var + 1e-5f);
            l = d * inv * w1;
            float s1 = fmaxf(warp_sum16(l * wl1), 0.0f);
            l = fmaf(s1, wl2, l);
            float mean2 = warp_sum16(l) * (1.0f / 11.0f);
            float d2 = on ? (l - mean2) : 0.f;
            float var2 = warp_sum16(d2 * d2) * (1.0f / 11.0f);
            float inv2 = rsqrtf(var2 + 1e-5f);
            if (on) pb[OF2 + c * 17 + row] = d2 * inv2 * w2;
        }
    }
    __syncthreads();

    // ---- kc/vc: thread = (px, which, h) ----
    {
        int h = tid & 31, which = (tid >> 5) & 1, px = tid >> 6;
        const float* A = which ? sAv : sAk;
        float* pb = &act[px * ACT];
        float a[10];
        #pragma unroll
        for (int p = 0; p < 10; p++) a[p] = A[h * 11 + p];
        float* dst = pb + (which ? OVC : OKC);
        #pragma unroll
        for (int c = 0; c < 11; c++) {
            float acc = 0.f;
            #pragma unroll
            for (int p = 0; p < 10; p++) acc = fmaf(pb[OF2 + c * 17 + p], a[p], acc);
            dst[h * 13 + c] = acc;
        }
    }
    __syncthreads();

    // ---- cross-attention (hd=1), no-max softmax ----
    {
        int h = lane, px = wrp & 3, ih = wrp >> 2;
        float* pb = &act[px * ACT];
        float kk[11], vv[11];
        #pragma unroll
        for (int j = 0; j < 11; j++) {
            kk[j] = pb[OKC + h * 13 + j];
            vv[j] = pb[OVC + h * 13 + j];
        }
        #pragma unroll
        for (int k = 0; k < 5; k++) {
            int i = ih * 5 + k;
            float q = sQc[i * 32 + h];
            float den = 0.f, num = 0.f;
            #pragma unroll
            for (int j = 0; j < 11; j++) {
                float e = __expf(q * kk[j]);
                den += e;
                num = fmaf(e, vv[j], num);
            }
            pb[OOA + i * 32 + h] = __fdividef(num, den);
        }
    }
    __syncthreads();

    // ---- CA out projection + residual ----
    {
        int c = lane, px = wrp & 3, ih = wrp >> 2;
        float* pb = &act[px * ACT];
        float w[32];
        #pragma unroll
        for (int hh = 0; hh < 32; hh++) w[hh] = sWo2[c * 33 + hh];
        #pragma unroll
        for (int k = 0; k < 5; k++) {
            int i = ih * 5 + k;
            const float4* o4 = (const float4*)&pb[OOA + i * 32];
            float acc = 0.f;
            #pragma unroll
            for (int q4 = 0; q4 < 8; q4++) {
                float4 m4 = o4[q4];
                acc = fmaf(w[4 * q4 + 0], m4.x, acc);
                acc = fmaf(w[4 * q4 + 1], m4.y, acc);
                acc = fmaf(w[4 * q4 + 2], m4.z, acc);
                acc = fmaf(w[4 * q4 + 3], m4.w, acc);
            }
            pb[OY2 + i * 33 + c] = sY1[i * 32 + c] + acc;
        }
    }
    __syncthreads();

    // ---- decoder LN2 + FFN + LN3 in place ----
    {
        float w2  = sDln2w[lane];
        float w3  = sDln3w[lane];
        float wl1 = sDlin1[lane];
        float wl2 = sDlin2[lane];
        for (int r = wrp; r < 40; r += 8) {
            int px = r & 3, i = r >> 2;
            float* row = &act[px * ACT + OY2 + i * 33];
            float l = row[lane];
            float mean = warp_sum(l) * (1.0f / 32.0f);
            float d = l - mean;
            float var = warp_sum(d * d) * (1.0f / 32.0f);
            float inv = rsqrtf(var + 1e-5f);
            l = d * inv * w2;
            float s1 = fmaxf(warp_sum(l * wl1), 0.0f);
            l = fmaf(s1, wl2, l);
            float mean2 = warp_sum(l) * (1.0f / 32.0f);
            float d2 = l - mean2;
            float var2 = warp_sum(d2 * d2) * (1.0f / 32.0f);
            float inv2 = rsqrtf(var2 + 1e-5f);
            row[lane] = d2 * inv2 * w3;
        }
    }
    __syncthreads();

    // ---- head: relu(y3 @ Wd0^T) ----
    for (int t = tid; t < 320; t += 256) {
        int i = t >> 5, px = (t >> 3) & 3, k = t & 7;
        float* pb = &act[px * ACT];
        float acc = 0.f;
        #pragma unroll 8
        for (int c = 0; c < 32; c++) acc = fmaf(sWd0[k * 33 + c], pb[OY2 + i * 33 + c], acc);
        pb[OHK + i * 8 + k] = fmaxf(acc, 0.0f);
    }
    __syncthreads();

    if (tid < 40) {
        int px = tid & 3, c = tid >> 2;
        float* pb = &act[px * ACT];
        float z = 0.f;
        #pragma unroll
        for (int k = 0; k < 8; k++) z = fmaf(pb[OHK + c * 8 + k], sWd1[k], z);
        out[((spn[px] * 10 + c) * 30 + sppi[px]) * 30 + sppj[px]] = z;
    }
}

extern "C" void kernel_launch(void* const* d_in, const int* in_sizes, int n_in,
                              void* d_out, int out_size) {
    const float* x       = (const float*)d_in[0];
    const float* Vf      = (const float*)d_in[1];
    const float* enc_in  = (const float*)d_in[2];
    const float* enc_out = (const float*)d_in[3];
    const float* el1     = (const float*)d_in[4];
    const float* el2     = (const float*)d_in[5];
    const float* eln1    = (const float*)d_in[6];
    const float* eln2    = (const float*)d_in[7];
    const float* ffv     = (const float*)d_in[8];
    const float* sa_in   = (const float*)d_in[9];
    const float* sa_out  = (const float*)d_in[10];
    const float* ca_in   = (const float*)d_in[11];
    const float* ca_out  = (const float*)d_in[12];
    const float* dl1     = (const float*)d_in[13];
    const float* dl2     = (const float*)d_in[14];
    const float* dln1    = (const float*)d_in[15];
    const float* dln2    = (const float*)d_in[16];
    const float* dln3    = (const float*)d_in[17];
    const float* wd0     = (const float*)d_in[18];
    const float* wd1     = (const float*)d_in[19];

    int ga = 1 + ((1 << 20) + 319) / 320;
    prologueA_kernel<<<ga, 320>>>(x, Vf, sa_in, sa_out, dln1, ca_in, ffv,
                                  enc_in, enc_out);
    prologueB_kernel<<<(1 << 19) / 256, 256>>>();
    main_kernel<<<3600, 256>>>(el1, el2, eln1, eln2, ca_out,
                               dl1, dl2, dln2, dln3, wd0, wd1,
                               (float*)d_out);
}